// round 3
// baseline (speedup 1.0000x reference)
#include <cuda_runtime.h>
#include <math.h>

#define NQb 12
#define SDIM 4096
#define TPB 256

typedef unsigned long long u64;

// ---------- packed f32x2 helpers (FFMA2 path, PTX-only per SASS_QUICKREF) ----------
__device__ __forceinline__ u64 pk2(float lo, float hi) {
    u64 r; asm("mov.b64 %0,{%1,%2};" : "=l"(r) : "f"(lo), "f"(hi)); return r;
}
__device__ __forceinline__ void unpk2(u64 v, float& lo, float& hi) {
    asm("mov.b64 {%0,%1},%2;" : "=f"(lo), "=f"(hi) : "l"(v));
}
__device__ __forceinline__ u64 f2mul(u64 a, u64 b) {
    u64 d; asm("mul.rn.f32x2 %0,%1,%2;" : "=l"(d) : "l"(a), "l"(b)); return d;
}
__device__ __forceinline__ u64 f2fma(u64 a, u64 b, u64 c) {
    u64 d; asm("fma.rn.f32x2 %0,%1,%2,%3;" : "=l"(d) : "l"(a), "l"(b), "l"(c)); return d;
}
__device__ __forceinline__ u64 cswap(u64 v) {  // (re,im) -> (im,re)
    float x, y; unpk2(v, x, y); return pk2(y, x);
}
// packed complex multiply: a * (br + i*bi)
__device__ __forceinline__ u64 cmulp(u64 a, float br, float bi) {
    return f2fma(pk2(-bi, bi), cswap(a), f2mul(pk2(br, br), a));
}
__device__ __forceinline__ u64 cmul2(u64 a, u64 b) {
    float br, bi; unpk2(b, br, bi); return cmulp(a, br, bi);
}

// smem slot swizzle (GF(2)-linear): conflict-free for all access patterns, 8B granularity
__device__ __forceinline__ int phi_idx(int k) { return k ^ ((k >> 4) & 31); }

// CNOT-chain permutation (VERIFIED in R1): state_after[k] = state_before[sigma(k)].
// Execution order: CNOT(11,0) step first, then p = 1..11 ASCENDING.
__device__ __forceinline__ int sigma12(int x) {
    x ^= (x & 1) << 11;
#pragma unroll
    for (int p = 1; p <= 11; ++p) x ^= ((x >> p) & 1) << (p - 1);
    return x;
}
// tau = sigma^{-1}: apply the involutive steps in REVERSE execution order:
// p = 11..1 descending, then the CNOT(11,0) step.
__device__ __forceinline__ int tau12(int x) {
#pragma unroll
    for (int p = 11; p >= 1; --p) x ^= ((x >> p) & 1) << (p - 1);
    x ^= (x & 1) << 11;
    return x;
}

// 4 RY rotations on 4 register bits; bit bb <-> qubit (qhi-bb). Packed re/im math.
__device__ __forceinline__ void ry4p(u64 a[16], const float* __restrict__ cryL,
                                     const float* __restrict__ sryL, int qhi) {
#pragma unroll
    for (int bb = 0; bb < 4; ++bb) {
        const float c = cryL[qhi - bb], s = sryL[qhi - bb];
        const u64 cc = pk2(c, c), ss = pk2(s, s), ns = pk2(-s, -s);
        const int m = 1 << bb;
#pragma unroll
        for (int j0 = 0; j0 < 16; ++j0) {
            if (j0 & m) continue;
            const int j1 = j0 | m;
            const u64 v0 = a[j0], v1 = a[j1];
            a[j0] = f2fma(ns, v1, f2mul(cc, v0));
            a[j1] = f2fma(ss, v0, f2mul(cc, v1));
        }
    }
}

__global__ void __launch_bounds__(TPB, 2)
qsim_kernel(const float* __restrict__ xin, const float* __restrict__ params,
            const float* __restrict__ lin_w, const float* __restrict__ lin_b,
            float* __restrict__ out) {
    __shared__ u64 samp[SDIM];               // packed (re,im) amplitudes, slot phi(k)
    __shared__ u64 TLs[16], TMs[16], THs[16];// layer-0 product-state tables
    __shared__ float2 sv[NQb][2];            // per-qubit 2-vectors after layer 0
    __shared__ float cry[60], sry[60], tz[60];   // layers 1..5 gates
    __shared__ float Tsum[5];
    __shared__ int sigArg[16], sigPhi[16], tauLo[16];
    __shared__ float red[TPB / 32];

    const int t = threadIdx.x;
    const int blk = blockIdx.x;

    // ---------- setup phase 1 ----------
    if (t < NQb) {
        const float h = tanhf(xin[blk * NQb + t]) * 1.5707963267948966f;
        const float ce = cosf(h), se = sinf(h);
        const float th = 0.5f * params[t];                  // layer-0 RY
        const float ct = cosf(th), st = sinf(th);
        const float a = ct * ce - st * se, b = st * ce + ct * se;
        const float tz0 = params[NQb + t];                  // layer-0 RZ
        const float c0 = cosf(0.5f * tz0), s0 = sinf(0.5f * tz0);
        sv[t][0] = make_float2(a * c0, -a * s0);            // a * e^{-i t/2}
        sv[t][1] = make_float2(b * c0,  b * s0);            // b * e^{+i t/2}
    }
    if (t < 60) {                                           // layers 1..5
        const int L = t / NQb, q = t - L * NQb;
        const float* pL = params + (L + 1) * 2 * NQb;
        const float th = 0.5f * pL[q];
        cry[t] = cosf(th); sry[t] = sinf(th);
        tz[t] = pL[NQb + q];
    }
    if (t < 16) {
        const int sa = sigma12(t << 8);
        sigArg[t] = sa;
        sigPhi[t] = phi_idx(sa);
        tauLo[t]  = tau12(t);
    }
    __syncthreads();
    // ---------- setup phase 2: product tables + RZ sums ----------
    if (t < 48) {
        const int g = t >> 4, n = t & 15;
        const int qbase = (g == 0) ? 11 : ((g == 1) ? 7 : 3);
        float2 acc = sv[qbase][n & 1];
        for (int p = 1; p < 4; ++p) {
            const float2 w = sv[qbase - p][(n >> p) & 1];
            acc = make_float2(acc.x * w.x - acc.y * w.y, acc.x * w.y + acc.y * w.x);
        }
        u64* tgt = (g == 0) ? TLs : ((g == 1) ? TMs : THs);
        tgt[n] = pk2(acc.x, acc.y);
    }
    if (t >= 48 && t < 53) {
        const int L = t - 48; float s = 0.f;
        for (int q = 0; q < NQb; ++q) s += tz[L * NQb + q];
        Tsum[L] = s;
    }
    __syncthreads();

    // ---------- per-thread invariants ----------
    const int sig_t = sigma12(t);
    const int baseg = phi_idx(sig_t);
    const int p0 = t ^ (t >> 4);                                   // phi(t)
    const int kb1 = (t & 15) | ((t >> 4) << 8);
    const int p1 = kb1 ^ (((t >> 4) & 1) << 4);                    // phi(kb1)
    const int p2 = (t << 4) ^ (t & 31);                            // phi(t<<4)
    const int tau_t = tau12(t << 4);

    // ---------- layer 1 pass-0 input via closed form (layer 0 + CNOT folded) ----------
    u64 amp[16];
#pragma unroll
    for (int j = 0; j < 16; ++j) {
        const int m = sig_t ^ sigArg[j];
        amp[j] = cmul2(cmul2(TLs[m & 15], TMs[(m >> 4) & 15]), THs[(m >> 8) & 15]);
    }

    float accm = 0.f;

#pragma unroll 1
    for (int L = 0; L < 5; ++L) {   // physical layers 1..5
        const float* cryL = cry + L * NQb;
        const float* sryL = sry + L * NQb;
        const float* tzL  = tz  + L * NQb;

        // pass 0: register bits 8-11 <-> qubits 3..0
        ry4p(amp, cryL, sryL, 3);
#pragma unroll
        for (int j = 0; j < 16; ++j)
            samp[p0 ^ ((j << 8) | ((j & 1) << 4))] = amp[j];
        __syncthreads();

        // pass 1: bits 4-7 <-> qubits 7..4
#pragma unroll
        for (int j = 0; j < 16; ++j) amp[j] = samp[p1 ^ ((j << 4) ^ j)];
        ry4p(amp, cryL, sryL, 7);
#pragma unroll
        for (int j = 0; j < 16; ++j) samp[p1 ^ ((j << 4) ^ j)] = amp[j];
        __syncthreads();

        // pass 2: bits 0-3 <-> qubits 11..8
#pragma unroll
        for (int j = 0; j < 16; ++j) amp[j] = samp[p2 ^ j];
        ry4p(amp, cryL, sryL, 11);

        if (L < 4) {
            // fused RZ: phase(k) = sum_q tz_q (bit_{11-q}(k) - 1/2), k = (t<<4)|j
            float phb = -0.5f * Tsum[L];
#pragma unroll
            for (int p = 0; p < 8; ++p)
                if ((t >> p) & 1) phb += tzL[7 - p];
#pragma unroll
            for (int j = 0; j < 16; ++j) {
                float ph = phb;
#pragma unroll
                for (int bb = 0; bb < 4; ++bb)
                    if ((j >> bb) & 1) ph += tzL[11 - bb];
                float sp, cp;
                __sincosf(ph, &sp, &cp);
                amp[j] = cmulp(amp[j], cp, sp);
            }
#pragma unroll
            for (int j = 0; j < 16; ++j) samp[p2 ^ j] = amp[j];
            __syncthreads();
            // CNOT fold: gather next layer's pass-0 groups
#pragma unroll
            for (int j = 0; j < 16; ++j) amp[j] = samp[baseg ^ sigPhi[j]];
            __syncthreads();
        } else {
            // last layer: RZ is |.|^2-invariant (skip); fold final CNOT into weights:
            // sum_k |post[k]|^2 w(k) = sum_m |pre[m]|^2 w(tau(m)),  m=(t<<4)|j
            u64 accp = 0ull;
#pragma unroll
            for (int j = 0; j < 16; ++j) {
                const int tm = tau_t ^ tauLo[j];
                const float w = (float)(NQb - 2 * __popc(tm));
                accp = f2fma(f2mul(amp[j], amp[j]), pk2(w, w), accp);
            }
            float wl, wh; unpk2(accp, wl, wh);
            accm = wl + wh;
        }
    }

    // ---------- reduction + head ----------
#pragma unroll
    for (int o = 16; o; o >>= 1) accm += __shfl_xor_sync(0xffffffffu, accm, o);
    if ((t & 31) == 0) red[t >> 5] = accm;
    __syncthreads();
    if (t == 0) {
        float m = 0.f;
#pragma unroll
        for (int w = 0; w < TPB / 32; ++w) m += red[w];
        const float z = (m / (float)NQb) * lin_w[0] + lin_b[0];
        out[blk] = 1.f / (1.f + expf(-z));
    }
}

extern "C" void kernel_launch(void* const* d_in, const int* in_sizes, int n_in,
                              void* d_out, int out_size) {
    const float* x      = (const float*)d_in[0];
    const float* params = (const float*)d_in[1];
    const float* lw     = (const float*)d_in[2];
    const float* lb     = (const float*)d_in[3];
    const int Bn = in_sizes[0] / NQb;
    qsim_kernel<<<Bn, TPB>>>(x, params, lw, lb, (float*)d_out);
}

// round 4
// speedup vs baseline: 1.4602x; 1.4602x over previous
#include <cuda_runtime.h>
#include <math.h>

#define NQb 12
#define SDIM 4096
#define TPB 64

typedef unsigned long long u64;

// ---------- packed f32x2 helpers ----------
__device__ __forceinline__ u64 pk2(float lo, float hi) {
    u64 r; asm("mov.b64 %0,{%1,%2};" : "=l"(r) : "f"(lo), "f"(hi)); return r;
}
__device__ __forceinline__ void unpk2(u64 v, float& lo, float& hi) {
    asm("mov.b64 {%0,%1},%2;" : "=f"(lo), "=f"(hi) : "l"(v));
}
__device__ __forceinline__ u64 f2mul(u64 a, u64 b) {
    u64 d; asm("mul.rn.f32x2 %0,%1,%2;" : "=l"(d) : "l"(a), "l"(b)); return d;
}
__device__ __forceinline__ u64 f2fma(u64 a, u64 b, u64 c) {
    u64 d; asm("fma.rn.f32x2 %0,%1,%2,%3;" : "=l"(d) : "l"(a), "l"(b), "l"(c)); return d;
}
__device__ __forceinline__ u64 cswap(u64 v) {
    float x, y; unpk2(v, x, y); return pk2(y, x);
}
// a * (br + i*bi), a packed (re,im)
__device__ __forceinline__ u64 cmulp(u64 a, float br, float bi) {
    return f2fma(pk2(-bi, bi), cswap(a), f2mul(pk2(br, br), a));
}
__device__ __forceinline__ u64 cmul2(u64 a, u64 b) {
    float br, bi; unpk2(b, br, bi); return cmulp(a, br, bi);
}

// smem slot swizzle: conflict-free for all four access patterns at 8B granularity
__device__ __forceinline__ int psi(int k) { return k ^ ((k >> 6) & 63); }

// CNOT-chain permutation (verified R1/R3): state_after[k] = state_before[sigma(k)]
__device__ __forceinline__ int sigma12(int x) {
    x ^= (x & 1) << 11;
#pragma unroll
    for (int p = 1; p <= 11; ++p) x ^= ((x >> p) & 1) << (p - 1);
    return x;
}
// tau = sigma^{-1} (verified R3): reverse step order
__device__ __forceinline__ int tau12(int x) {
#pragma unroll
    for (int p = 11; p >= 1; --p) x ^= ((x >> p) & 1) << (p - 1);
    x ^= (x & 1) << 11;
    return x;
}

// 6 RY rotations on the 6 register bits of a 64-amplitude group.
// reg bit bb <-> qubit (QOFF - bb); gate [[c,-s],[s,c]] on (bit=0, bit=1).
template <int QOFF>
__device__ __forceinline__ void ry6(u64 a[64], const float* __restrict__ cryL,
                                    const float* __restrict__ sryL) {
#pragma unroll
    for (int bb = 0; bb < 6; ++bb) {
        const float c = cryL[QOFF - bb], s = sryL[QOFF - bb];
        const u64 cc = pk2(c, c), ss = pk2(s, s), ns = pk2(-s, -s);
        const int m = 1 << bb;
#pragma unroll
        for (int j0 = 0; j0 < 64; ++j0) {
            if (j0 & m) continue;       // compile-time pruned
            const int j1 = j0 | m;
            const u64 v0 = a[j0], v1 = a[j1];
            a[j0] = f2fma(ns, v1, f2mul(cc, v0));
            a[j1] = f2fma(ss, v0, f2mul(cc, v1));
        }
    }
}

__global__ void __launch_bounds__(TPB, 5)
qsim_kernel(const float* __restrict__ xin, const float* __restrict__ params,
            const float* __restrict__ lin_w, const float* __restrict__ lin_b,
            float* __restrict__ out) {
    __shared__ u64 samp[SDIM];            // packed (re,im), slot psi(k) (or psi(tau(k)) post-CNOT)
    __shared__ u64 TLs[64], THs[64];      // layer-0 product tables (qubits 11..6 / 5..0)
    __shared__ float2 sv[NQb][2];         // per-qubit 2-vectors after layer 0
    __shared__ float cry[60], sry[60];    // RY cos/sin, layers 1..5
    __shared__ float tz[48];              // RZ angles, layers 1..4 (layer-5 RZ is |.|^2-invariant)
    __shared__ float Tsum[4];
    __shared__ float zoff[64];            // per-layer RZ phase offsets for the j-bits
    __shared__ float red2[2];

    const int t = threadIdx.x;
    const int blk = blockIdx.x;

    // ---------- setup phase 1 ----------
    if (t < NQb) {
        const float h = tanhf(xin[blk * NQb + t]) * 1.5707963267948966f;
        const float ce = cosf(h), se = sinf(h);
        const float th = 0.5f * params[t];                  // layer-0 RY
        const float ct = cosf(th), st = sinf(th);
        const float a = ct * ce - st * se, b = st * ce + ct * se;
        const float t0 = params[NQb + t];                   // layer-0 RZ
        const float c0 = cosf(0.5f * t0), s0 = sinf(0.5f * t0);
        sv[t][0] = make_float2(a * c0, -a * s0);
        sv[t][1] = make_float2(b * c0,  b * s0);
    }
    if (t < 60) {                                           // RY layers 1..5
        const int L = t / NQb, q = t - L * NQb;
        const float th = 0.5f * params[(L + 1) * 24 + q];
        cry[t] = cosf(th); sry[t] = sinf(th);
    }
    if (t < 48) {                                           // RZ layers 1..4
        const int L = t / NQb, q = t - L * NQb;
        tz[t] = params[(L + 1) * 24 + NQb + q];
    }
    __syncthreads();

    // ---------- setup phase 2: product tables, RZ totals ----------
    {
        // TL[n] = prod_{p=0..5} sv[11-p][n_p]   (k bits 0-5 <-> qubits 11..6)
        float2 a = sv[11][t & 1];
#pragma unroll
        for (int p = 1; p < 6; ++p) {
            const float2 w = sv[11 - p][(t >> p) & 1];
            a = make_float2(a.x * w.x - a.y * w.y, a.x * w.y + a.y * w.x);
        }
        TLs[t] = pk2(a.x, a.y);
        // TH[n] = prod_{p=0..5} sv[5-p][n_p]    (k bits 6-11 <-> qubits 5..0)
        float2 b = sv[5][t & 1];
#pragma unroll
        for (int p = 1; p < 6; ++p) {
            const float2 w = sv[5 - p][(t >> p) & 1];
            b = make_float2(b.x * w.x - b.y * w.y, b.x * w.y + b.y * w.x);
        }
        THs[t] = pk2(b.x, b.y);
    }
    if (t < 4) {
        float s = 0.f;
#pragma unroll
        for (int q = 0; q < NQb; ++q) s += tz[t * NQb + q];
        Tsum[t] = s;
    }
    __syncthreads();

    // ---------- per-thread invariants ----------
    const int S_t  = sigma12(t << 6);     // sigma of the thread's high bits
    const int Ct   = (t << 6) ^ t;        // psi(t<<6)  (pass-A base)
    const int ptT  = psi(tau12(t));       // storeB tau-fold, t-part
    const int tau_t = tau12(t);           // measurement fold

    // ---------- layer-1 pass-A input: layer0 + CNOT folded, kA=(t<<6)|j ----------
    u64 amp[64];
#pragma unroll
    for (int j = 0; j < 64; ++j) {
        const int m = S_t ^ sigma12(j);
        amp[j] = cmul2(TLs[m & 63], THs[(m >> 6) & 63]);
    }

    float accm = 0.f;

#pragma unroll 1
    for (int L = 0; L < 5; ++L) {         // physical layers 1..5
        const float* cryL = cry + L * NQb;
        const float* sryL = sry + L * NQb;

        if (L) {                          // pass-A load: plain own-slot read (CNOT pre-folded)
#pragma unroll
            for (int j = 0; j < 64; ++j) amp[j] = samp[Ct ^ j];
        }

        float phb = 0.f;
        if (L < 4) {                      // RZ prep: zoff[j-part] table + per-thread base
            const float* tzL = tz + L * NQb;
            float zo = 0.f;
            phb = -0.5f * Tsum[L];
#pragma unroll
            for (int p = 0; p < 6; ++p) {
                if ((t >> p) & 1) { zo += tzL[5 - p]; phb += tzL[11 - p]; }
            }
            zoff[t] = zo;
        }

        // pass A: reg bits = k bits 0-5 <-> qubits 11..6
        ry6<11>(amp, cryL, sryL);
#pragma unroll
        for (int j = 0; j < 64; ++j) samp[Ct ^ j] = amp[j];   // own slots: no read hazard
        __syncthreads();

        // pass B: kB=(j<<6)|t, reg bits = k bits 6-11 <-> qubits 5..0
#pragma unroll
        for (int j = 0; j < 64; ++j) amp[j] = samp[((j << 6) ^ j) ^ t];
        ry6<5>(amp, cryL, sryL);

        if (L < 4) {
            // fused RZ: phase(kB) = phb(t) + zoff[j]
#pragma unroll
            for (int j = 0; j < 64; ++j) {
                float sp, cp;
                __sincosf(phb + zoff[j], &sp, &cp);
                amp[j] = cmulp(amp[j], cp, sp);
            }
            // storeB with CNOT fold: amp(kB) -> slot psi(tau(kB))
#pragma unroll
            for (int j = 0; j < 64; ++j)
                samp[psi(tau12(j << 6)) ^ ptT] = amp[j];
            __syncthreads();
        } else {
            // last layer: RZ dropped (phase-only); fold final CNOT into weights:
            // sum_r |post[r]|^2 w(r) = sum_m |pre[m]|^2 w(tau(m)), m = kB
            u64 accp = 0ull;
#pragma unroll
            for (int j = 0; j < 64; ++j) {
                const int tm = tau12(j << 6) ^ tau_t;
                const float w = (float)(NQb - 2 * __popc(tm));
                accp = f2fma(f2mul(amp[j], amp[j]), pk2(w, w), accp);
            }
            float wl, wh; unpk2(accp, wl, wh);
            accm = wl + wh;
        }
    }

    // ---------- reduction (64 threads = 2 warps) + head ----------
#pragma unroll
    for (int o = 16; o; o >>= 1) accm += __shfl_xor_sync(0xffffffffu, accm, o);
    if ((t & 31) == 0) red2[t >> 5] = accm;
    __syncthreads();
    if (t == 0) {
        const float m = red2[0] + red2[1];
        const float z = (m / (float)NQb) * lin_w[0] + lin_b[0];
        out[blk] = 1.f / (1.f + expf(-z));
    }
}

extern "C" void kernel_launch(void* const* d_in, const int* in_sizes, int n_in,
                              void* d_out, int out_size) {
    const float* x      = (const float*)d_in[0];
    const float* params = (const float*)d_in[1];
    const float* lw     = (const float*)d_in[2];
    const float* lb     = (const float*)d_in[3];
    const int Bn = in_sizes[0] / NQb;     // 512
    qsim_kernel<<<Bn, TPB>>>(x, params, lw, lb, (float*)d_out);
}

// round 5
// speedup vs baseline: 1.5851x; 1.0855x over previous
#include <cuda_runtime.h>
#include <math.h>

#define NQb 12
#define SDIM 4096
#define TPB 128

typedef unsigned long long u64;
typedef unsigned int u32;

// ---------- packed f32x2 helpers ----------
__device__ __forceinline__ u64 pk2(float lo, float hi) {
    u64 r; asm("mov.b64 %0,{%1,%2};" : "=l"(r) : "f"(lo), "f"(hi)); return r;
}
__device__ __forceinline__ void unpk2(u64 v, float& lo, float& hi) {
    asm("mov.b64 {%0,%1},%2;" : "=f"(lo), "=f"(hi) : "l"(v));
}
__device__ __forceinline__ u64 f2mul(u64 a, u64 b) {
    u64 d; asm("mul.rn.f32x2 %0,%1,%2;" : "=l"(d) : "l"(a), "l"(b)); return d;
}
__device__ __forceinline__ u64 f2fma(u64 a, u64 b, u64 c) {
    u64 d; asm("fma.rn.f32x2 %0,%1,%2,%3;" : "=l"(d) : "l"(a), "l"(b), "l"(c)); return d;
}
__device__ __forceinline__ u64 cswap(u64 v) {
    float x, y; unpk2(v, x, y); return pk2(y, x);
}
__device__ __forceinline__ u64 cmulp(u64 a, float br, float bi) {   // a*(br+i bi)
    return f2fma(pk2(-bi, bi), cswap(a), f2mul(pk2(br, br), a));
}
__device__ __forceinline__ u64 cmul2(u64 a, u64 b) {
    float br, bi; unpk2(b, br, bi); return cmulp(a, br, bi);
}

// swizzle: conflict-free at 8B granularity for pass-A, pass-B, tau-store patterns
__device__ __forceinline__ int psi(int k) {
    return k ^ ((k >> 5) & 31) ^ (((k >> 10) & 3) << 3);
}

// CNOT-chain permutation (verified R1/R3): state_after[k] = state_before[sigma(k)]
__device__ __forceinline__ int sigma12(int x) {
    x ^= (x & 1) << 11;
#pragma unroll
    for (int p = 1; p <= 11; ++p) x ^= ((x >> p) & 1) << (p - 1);
    return x;
}
// tau = sigma^{-1}
__device__ __forceinline__ int tau12(int x) {
#pragma unroll
    for (int p = 11; p >= 1; --p) x ^= ((x >> p) & 1) << (p - 1);
    x ^= (x & 1) << 11;
    return x;
}

// 5 RY rotations on the 5 register bits; reg bit bb <-> qubit (QHI-bb)
template <int QHI>
__device__ __forceinline__ void ry5(u64 a[32], const float* __restrict__ cryL,
                                    const float* __restrict__ sryL) {
#pragma unroll
    for (int bb = 0; bb < 5; ++bb) {
        const float c = cryL[QHI - bb], s = sryL[QHI - bb];
        const u64 cc = pk2(c, c), ss = pk2(s, s), ns = pk2(-s, -s);
        const int m = 1 << bb;
#pragma unroll
        for (int j0 = 0; j0 < 32; ++j0) {
            if (j0 & m) continue;        // compile-time pruned
            const int j1 = j0 | m;
            const u64 v0 = a[j0], v1 = a[j1];
            a[j0] = f2fma(ns, v1, f2mul(cc, v0));
            a[j1] = f2fma(ss, v0, f2mul(cc, v1));
        }
    }
}

__global__ void __launch_bounds__(TPB, 4)
qsim_kernel(const float* __restrict__ xin, const float* __restrict__ params,
            const float* __restrict__ lin_w, const float* __restrict__ lin_b,
            float* __restrict__ out) {
    __shared__ u64 samp[SDIM];             // packed (re,im), slot psi(k) (tau-folded post-CNOT)
    __shared__ u64 TLs[64], THs[64];       // layer-0 product tables
    __shared__ float2 sv[NQb][2];
    __shared__ float cry[60], sry[60];     // RY cos/sin, layers 1..5
    __shared__ float tz[48];               // RZ angles, layers 1..4
    __shared__ float zoffB[4][32];         // RZ phase offsets for pass-B reg bits (qubits 6..2)
    __shared__ float Tsum[4];
    __shared__ float red4[4];

    const int t = threadIdx.x;
    const int blk = blockIdx.x;
    const int lane = t & 31;

    // ---------- setup ----------
    if (t < NQb) {
        const float h = tanhf(xin[blk * NQb + t]) * 1.5707963267948966f;
        const float ce = cosf(h), se = sinf(h);
        const float th = 0.5f * params[t];
        const float ct = cosf(th), st = sinf(th);
        const float a = ct * ce - st * se, b = st * ce + ct * se;
        const float t0 = params[NQb + t];
        const float c0 = cosf(0.5f * t0), s0 = sinf(0.5f * t0);
        sv[t][0] = make_float2(a * c0, -a * s0);
        sv[t][1] = make_float2(b * c0,  b * s0);
    }
    if (t < 60) {
        const int L = t / NQb, q = t - L * NQb;
        const float th = 0.5f * params[(L + 1) * 24 + q];
        cry[t] = cosf(th); sry[t] = sinf(th);
    }
    if (t < 48) {
        const int L = t / NQb, q = t - L * NQb;
        tz[t] = params[(L + 1) * 24 + NQb + q];
    }
    __syncthreads();

    // product tables: TL over qubits 11..6 (k bits 0-5), TH over qubits 5..0 (bits 6-11)
    {
        const int n = t & 63;
        const int qb = (t < 64) ? 11 : 5;
        float2 a = sv[qb][n & 1];
#pragma unroll
        for (int p = 1; p < 6; ++p) {
            const float2 w = sv[qb - p][(n >> p) & 1];
            a = make_float2(a.x * w.x - a.y * w.y, a.x * w.y + a.y * w.x);
        }
        if (t < 64) TLs[n] = pk2(a.x, a.y); else THs[n] = pk2(a.x, a.y);
    }
    {   // zoffB[L][j]: pass-B reg bit bb <-> qubit (6-bb)
        const int L = t >> 5, j = t & 31;
        const float* tzL = tz + L * NQb;
        float zo = 0.f;
#pragma unroll
        for (int bb = 0; bb < 5; ++bb)
            if ((j >> bb) & 1) zo += tzL[6 - bb];
        zoffB[L][j] = zo;
    }
    if (t < 4) {
        float s = 0.f;
#pragma unroll
        for (int q = 0; q < NQb; ++q) s += tz[t * NQb + q];
        Tsum[t] = s;
    }
    __syncthreads();

    // ---------- per-thread invariants ----------
    // pass A: kA = (t<<5)|j ; slot = A_t ^ j
    const int A_t = (t << 5) ^ (t & 31) ^ (((t >> 5) & 3) << 3);
    // pass B: kB = (t&7) | (((t>>5)&3)<<3) | (j<<5) | (((t>>3)&3)<<10)
    const int w2 = (t >> 5) & 3, h2 = (t >> 3) & 3;
    const int kBt = (t & 7) | (w2 << 3) | (h2 << 10);
    const int B_t = kBt ^ (h2 << 3);               // slot = B_t ^ ((j<<5)^j)
    const int PT_t = psi(tau12(kBt));              // tau-fold store, t-part
    const int TAU_t = tau12(kBt);                  // measurement fold

    // per-layer RZ base phase for the t-part bits of kB
    float phb[4];
#pragma unroll
    for (int L = 0; L < 4; ++L) {
        const float* tzL = tz + L * NQb;
        float p = -0.5f * Tsum[L];
        if (t & 1)  p += tzL[11];
        if (t & 2)  p += tzL[10];
        if (t & 4)  p += tzL[9];
        if (t & 32) p += tzL[8];
        if (t & 64) p += tzL[7];
        if (t & 8)  p += tzL[1];
        if (t & 16) p += tzL[0];
        phb[L] = p;
    }

    // ---------- layer-1 pass-A input: layer 0 + CNOT folded ----------
    const int S_t = sigma12(t << 5);
    u64 amp[32];
#pragma unroll
    for (int j = 0; j < 32; ++j) {
        const int m = S_t ^ sigma12(j);
        amp[j] = cmul2(TLs[m & 63], THs[(m >> 6) & 63]);
    }

    float accm = 0.f;

#pragma unroll 1
    for (int L = 0; L < 5; ++L) {          // physical layers 1..5
        const float* cryL = cry + L * NQb;
        const float* sryL = sry + L * NQb;

        // pass A: qubits 11..7 on reg bits (own slots — CNOT pre-folded by tau-store)
        if (L) {
#pragma unroll
            for (int j = 0; j < 32; ++j) amp[j] = samp[A_t ^ j];
        }
        ry5<11>(amp, cryL, sryL);
#pragma unroll
        for (int j = 0; j < 32; ++j) samp[A_t ^ j] = amp[j];
        __syncthreads();

        // pass B: qubits 6..2 on reg bits
#pragma unroll
        for (int j = 0; j < 32; ++j) amp[j] = samp[B_t ^ ((j << 5) ^ j)];
        ry5<6>(amp, cryL, sryL);

        // qubit 1 (k bit 10 <-> lane bit 3) and qubit 0 (k bit 11 <-> lane bit 4) via shfl
        {
            const float c1 = cryL[1], s1 = sryL[1];
            const u64 cc1 = pk2(c1, c1);
            const float g1 = (lane & 8) ? s1 : -s1;
            const u64 sg1 = pk2(g1, g1);
#pragma unroll
            for (int j = 0; j < 32; ++j) {
                const u64 p = __shfl_xor_sync(0xffffffffu, amp[j], 8);
                amp[j] = f2fma(sg1, p, f2mul(cc1, amp[j]));
            }
            const float c0 = cryL[0], s0 = sryL[0];
            const u64 cc0 = pk2(c0, c0);
            const float g0 = (lane & 16) ? s0 : -s0;
            const u64 sg0 = pk2(g0, g0);
#pragma unroll
            for (int j = 0; j < 32; ++j) {
                const u64 p = __shfl_xor_sync(0xffffffffu, amp[j], 16);
                amp[j] = f2fma(sg0, p, f2mul(cc0, amp[j]));
            }
        }

        if (L < 4) {
            // fused RZ: phase(kB) = phb[L](t) + zoffB[L][j]
            const float* zoL = zoffB[L];
#pragma unroll
            for (int j = 0; j < 32; ++j) {
                float sp, cp;
                __sincosf(phb[L] + zoL[j], &sp, &cp);
                amp[j] = cmulp(amp[j], cp, sp);
            }
            __syncthreads();   // all pass-B loads consumed before permuted overwrite
            // CNOT fold: amp(kB) -> slot psi(tau(kB))
#pragma unroll
            for (int j = 0; j < 32; ++j)
                samp[PT_t ^ psi(tau12(j << 5))] = amp[j];
            __syncthreads();
        } else {
            // last layer: RZ is |.|^2-invariant; fold final CNOT into weights
            u64 accp = 0ull;
#pragma unroll
            for (int j = 0; j < 32; ++j) {
                const int tm = TAU_t ^ tau12(j << 5);
                const float w = (float)(NQb - 2 * __popc(tm));
                accp = f2fma(f2mul(amp[j], amp[j]), pk2(w, w), accp);
            }
            float wl, wh; unpk2(accp, wl, wh);
            accm = wl + wh;
        }
    }

    // ---------- reduction (4 warps) + head ----------
#pragma unroll
    for (int o = 16; o; o >>= 1) accm += __shfl_xor_sync(0xffffffffu, accm, o);
    if (lane == 0) red4[t >> 5] = accm;
    __syncthreads();
    if (t == 0) {
        const float m = red4[0] + red4[1] + red4[2] + red4[3];
        const float z = (m / (float)NQb) * lin_w[0] + lin_b[0];
        out[blk] = 1.f / (1.f + expf(-z));
    }
}

extern "C" void kernel_launch(void* const* d_in, const int* in_sizes, int n_in,
                              void* d_out, int out_size) {
    const float* x      = (const float*)d_in[0];
    const float* params = (const float*)d_in[1];
    const float* lw     = (const float*)d_in[2];
    const float* lb     = (const float*)d_in[3];
    const int Bn = in_sizes[0] / NQb;      // 512
    qsim_kernel<<<Bn, TPB>>>(x, params, lw, lb, (float*)d_out);
}

// round 6
// speedup vs baseline: 1.5932x; 1.0051x over previous
#include <cuda_runtime.h>
#include <math.h>

#define NQb 12
#define SDIM 4096
#define TPB 128

typedef unsigned long long u64;
typedef unsigned int u32;

// ---------- packed f32x2 helpers ----------
__device__ __forceinline__ u64 pk2(float lo, float hi) {
    u64 r; asm("mov.b64 %0,{%1,%2};" : "=l"(r) : "f"(lo), "f"(hi)); return r;
}
__device__ __forceinline__ void unpk2(u64 v, float& lo, float& hi) {
    asm("mov.b64 {%0,%1},%2;" : "=f"(lo), "=f"(hi) : "l"(v));
}
__device__ __forceinline__ u64 f2mul(u64 a, u64 b) {
    u64 d; asm("mul.rn.f32x2 %0,%1,%2;" : "=l"(d) : "l"(a), "l"(b)); return d;
}
__device__ __forceinline__ u64 f2fma(u64 a, u64 b, u64 c) {
    u64 d; asm("fma.rn.f32x2 %0,%1,%2,%3;" : "=l"(d) : "l"(a), "l"(b), "l"(c)); return d;
}
__device__ __forceinline__ u64 cswap(u64 v) {
    float x, y; unpk2(v, x, y); return pk2(y, x);
}
__device__ __forceinline__ u64 cmulp(u64 a, float br, float bi) {   // a*(br+i bi)
    return f2fma(pk2(-bi, bi), cswap(a), f2mul(pk2(br, br), a));
}
__device__ __forceinline__ u64 cmul2(u64 a, u64 b) {
    float br, bi; unpk2(b, br, bi); return cmulp(a, br, bi);
}

// swizzle: conflict-free at 8B granularity for pass-A, pass-B, tau-store patterns
__device__ __forceinline__ int psi(int k) {
    return k ^ ((k >> 5) & 31) ^ (((k >> 10) & 3) << 3);
}

// CNOT-chain permutation (verified R1/R3): state_after[k] = state_before[sigma(k)]
__device__ __forceinline__ int sigma12(int x) {
    x ^= (x & 1) << 11;
#pragma unroll
    for (int p = 1; p <= 11; ++p) x ^= ((x >> p) & 1) << (p - 1);
    return x;
}
// tau = sigma^{-1}
__device__ __forceinline__ int tau12(int x) {
#pragma unroll
    for (int p = 11; p >= 1; --p) x ^= ((x >> p) & 1) << (p - 1);
    x ^= (x & 1) << 11;
    return x;
}

// 5 RY rotations on the 5 register bits; reg bit bb <-> qubit (QHI-bb)
template <int QHI>
__device__ __forceinline__ void ry5(u64 a[32], const float* __restrict__ cryL,
                                    const float* __restrict__ sryL) {
#pragma unroll
    for (int bb = 0; bb < 5; ++bb) {
        const float c = cryL[QHI - bb], s = sryL[QHI - bb];
        const u64 cc = pk2(c, c), ss = pk2(s, s), ns = pk2(-s, -s);
        const int m = 1 << bb;
#pragma unroll
        for (int j0 = 0; j0 < 32; ++j0) {
            if (j0 & m) continue;        // compile-time pruned
            const int j1 = j0 | m;
            const u64 v0 = a[j0], v1 = a[j1];
            a[j0] = f2fma(ns, v1, f2mul(cc, v0));
            a[j1] = f2fma(ss, v0, f2mul(cc, v1));
        }
    }
}

__global__ void __launch_bounds__(TPB, 4)
qsim_kernel(const float* __restrict__ xin, const float* __restrict__ params,
            const float* __restrict__ lin_w, const float* __restrict__ lin_b,
            float* __restrict__ out) {
    __shared__ u64 samp[SDIM];             // packed (re,im), slot psi(k) (tau-folded post-CNOT)
    __shared__ u64 TLs[64], THs[64];       // layer-0 product tables
    __shared__ float2 sv[NQb][2];
    __shared__ float cry[60], sry[60];     // RY cos/sin, layers 1..5
    __shared__ float tz[48];               // RZ angles, layers 1..4
    __shared__ float zoffB[4][32];         // RZ phase offsets for pass-B reg bits (qubits 6..2)
    __shared__ float Tsum[4];
    __shared__ float red4[4];

    const int t = threadIdx.x;
    const int blk = blockIdx.x;
    const int lane = t & 31;

    // ---------- setup ----------
    if (t < NQb) {
        const float h = tanhf(xin[blk * NQb + t]) * 1.5707963267948966f;
        const float ce = cosf(h), se = sinf(h);
        const float th = 0.5f * params[t];
        const float ct = cosf(th), st = sinf(th);
        const float a = ct * ce - st * se, b = st * ce + ct * se;
        const float t0 = params[NQb + t];
        const float c0 = cosf(0.5f * t0), s0 = sinf(0.5f * t0);
        sv[t][0] = make_float2(a * c0, -a * s0);
        sv[t][1] = make_float2(b * c0,  b * s0);
    }
    if (t < 60) {
        const int L = t / NQb, q = t - L * NQb;
        const float th = 0.5f * params[(L + 1) * 24 + q];
        cry[t] = cosf(th); sry[t] = sinf(th);
    }
    if (t < 48) {
        const int L = t / NQb, q = t - L * NQb;
        tz[t] = params[(L + 1) * 24 + NQb + q];
    }
    __syncthreads();

    // product tables: TL over qubits 11..6 (k bits 0-5), TH over qubits 5..0 (bits 6-11)
    {
        const int n = t & 63;
        const int qb = (t < 64) ? 11 : 5;
        float2 a = sv[qb][n & 1];
#pragma unroll
        for (int p = 1; p < 6; ++p) {
            const float2 w = sv[qb - p][(n >> p) & 1];
            a = make_float2(a.x * w.x - a.y * w.y, a.x * w.y + a.y * w.x);
        }
        if (t < 64) TLs[n] = pk2(a.x, a.y); else THs[n] = pk2(a.x, a.y);
    }
    {   // zoffB[L][j]: pass-B reg bit bb <-> qubit (6-bb)
        const int L = t >> 5, j = t & 31;
        const float* tzL = tz + L * NQb;
        float zo = 0.f;
#pragma unroll
        for (int bb = 0; bb < 5; ++bb)
            if ((j >> bb) & 1) zo += tzL[6 - bb];
        zoffB[L][j] = zo;
    }
    if (t < 4) {
        float s = 0.f;
#pragma unroll
        for (int q = 0; q < NQb; ++q) s += tz[t * NQb + q];
        Tsum[t] = s;
    }
    __syncthreads();

    // ---------- per-thread invariants ----------
    // pass A: kA = (t<<5)|j ; slot = A_t ^ j
    const int A_t = (t << 5) ^ (t & 31) ^ (((t >> 5) & 3) << 3);
    // pass B: kB = (t&7) | (((t>>5)&3)<<3) | (j<<5) | (((t>>3)&3)<<10)
    const int w2 = (t >> 5) & 3, h2 = (t >> 3) & 3;
    const int kBt = (t & 7) | (w2 << 3) | (h2 << 10);
    const int B_t = kBt ^ (h2 << 3);               // slot = B_t ^ ((j<<5)^j)
    const int PT_t = psi(tau12(kBt));              // tau-fold store, t-part
    const int TAU_t = tau12(kBt);                  // measurement fold

    // per-layer RZ base phase for the t-part bits of kB
    float phb[4];
#pragma unroll
    for (int L = 0; L < 4; ++L) {
        const float* tzL = tz + L * NQb;
        float p = -0.5f * Tsum[L];
        if (t & 1)  p += tzL[11];
        if (t & 2)  p += tzL[10];
        if (t & 4)  p += tzL[9];
        if (t & 32) p += tzL[8];
        if (t & 64) p += tzL[7];
        if (t & 8)  p += tzL[1];
        if (t & 16) p += tzL[0];
        phb[L] = p;
    }

    // ---------- layer-1 pass-A input: layer 0 + CNOT folded ----------
    const int S_t = sigma12(t << 5);
    u64 amp[32];
#pragma unroll
    for (int j = 0; j < 32; ++j) {
        const int m = S_t ^ sigma12(j);
        amp[j] = cmul2(TLs[m & 63], THs[(m >> 6) & 63]);
    }

    float accm = 0.f;

#pragma unroll 1
    for (int L = 0; L < 5; ++L) {          // physical layers 1..5
        const float* cryL = cry + L * NQb;
        const float* sryL = sry + L * NQb;

        // pass A: qubits 11..7 on reg bits (own slots — CNOT pre-folded by tau-store)
        if (L) {
#pragma unroll
            for (int j = 0; j < 32; ++j) amp[j] = samp[A_t ^ j];
        }
        ry5<11>(amp, cryL, sryL);
#pragma unroll
        for (int j = 0; j < 32; ++j) samp[A_t ^ j] = amp[j];
        __syncthreads();

        // pass B: qubits 6..2 on reg bits
#pragma unroll
        for (int j = 0; j < 32; ++j) amp[j] = samp[B_t ^ ((j << 5) ^ j)];
        ry5<6>(amp, cryL, sryL);

        // qubit 1 (k bit 10 <-> lane bit 3) and qubit 0 (k bit 11 <-> lane bit 4) via shfl
        {
            const float c1 = cryL[1], s1 = sryL[1];
            const u64 cc1 = pk2(c1, c1);
            const float g1 = (lane & 8) ? s1 : -s1;
            const u64 sg1 = pk2(g1, g1);
#pragma unroll
            for (int j = 0; j < 32; ++j) {
                const u64 p = __shfl_xor_sync(0xffffffffu, amp[j], 8);
                amp[j] = f2fma(sg1, p, f2mul(cc1, amp[j]));
            }
            const float c0 = cryL[0], s0 = sryL[0];
            const u64 cc0 = pk2(c0, c0);
            const float g0 = (lane & 16) ? s0 : -s0;
            const u64 sg0 = pk2(g0, g0);
#pragma unroll
            for (int j = 0; j < 32; ++j) {
                const u64 p = __shfl_xor_sync(0xffffffffu, amp[j], 16);
                amp[j] = f2fma(sg0, p, f2mul(cc0, amp[j]));
            }
        }

        if (L < 4) {
            // fused RZ: phase(kB) = phb[L](t) + zoffB[L][j]
            const float* zoL = zoffB[L];
#pragma unroll
            for (int j = 0; j < 32; ++j) {
                float sp, cp;
                __sincosf(phb[L] + zoL[j], &sp, &cp);
                amp[j] = cmulp(amp[j], cp, sp);
            }
            __syncthreads();   // all pass-B loads consumed before permuted overwrite
            // CNOT fold: amp(kB) -> slot psi(tau(kB))
#pragma unroll
            for (int j = 0; j < 32; ++j)
                samp[PT_t ^ psi(tau12(j << 5))] = amp[j];
            __syncthreads();
        } else {
            // last layer: RZ is |.|^2-invariant; fold final CNOT into weights
            u64 accp = 0ull;
#pragma unroll
            for (int j = 0; j < 32; ++j) {
                const int tm = TAU_t ^ tau12(j << 5);
                const float w = (float)(NQb - 2 * __popc(tm));
                accp = f2fma(f2mul(amp[j], amp[j]), pk2(w, w), accp);
            }
            float wl, wh; unpk2(accp, wl, wh);
            accm = wl + wh;
        }
    }

    // ---------- reduction (4 warps) + head ----------
#pragma unroll
    for (int o = 16; o; o >>= 1) accm += __shfl_xor_sync(0xffffffffu, accm, o);
    if (lane == 0) red4[t >> 5] = accm;
    __syncthreads();
    if (t == 0) {
        const float m = red4[0] + red4[1] + red4[2] + red4[3];
        const float z = (m / (float)NQb) * lin_w[0] + lin_b[0];
        out[blk] = 1.f / (1.f + expf(-z));
    }
}

extern "C" void kernel_launch(void* const* d_in, const int* in_sizes, int n_in,
                              void* d_out, int out_size) {
    const float* x      = (const float*)d_in[0];
    const float* params = (const float*)d_in[1];
    const float* lw     = (const float*)d_in[2];
    const float* lb     = (const float*)d_in[3];
    const int Bn = in_sizes[0] / NQb;      // 512
    qsim_kernel<<<Bn, TPB>>>(x, params, lw, lb, (float*)d_out);
}